// round 11
// baseline (speedup 1.0000x reference)
#include <cuda_runtime.h>
#include <cuda_bf16.h>
#include <stdint.h>
#include <math.h>

// Problem dims (fixed by the dataset)
#define D_MODEL 2048
#define D_FF    8192
#define NTOK    8192            // B*S = 4*2048
#define NW      ((size_t)D_FF * D_MODEL)

// ---------------- scratch (device globals: allocation-free rule) -----------
__device__ __nv_bfloat16 g_w1q[D_FF * D_MODEL];   // 32 MB  ternary as bf16
__device__ __nv_bfloat16 g_w2q[D_MODEL * D_FF];   // 32 MB
__device__ __nv_bfloat16 g_xq [NTOK * D_MODEL];   // 32 MB  int8 values as bf16
__device__ __nv_bfloat16 g_hq [NTOK * D_FF];      // 128 MB
__device__ float  g_h  [NTOK * D_FF];             // 256 MB (fp32: rounding fidelity)
__device__ float  g_fx [NTOK];
__device__ float  g_fh [NTOK];
__device__ float  g_part[1024];
__device__ float  g_s1, g_s2;

// ---------------- PTX helpers (baseline ISA only: sm_80-era) ----------------
__device__ __forceinline__ uint32_t smem_u32(const void* p) {
    uint32_t a;
    asm("{ .reg .u64 t; cvta.to.shared.u64 t, %1; cvt.u32.u64 %0, t; }" : "=r"(a) : "l"(p));
    return a;
}
__device__ __forceinline__ void cp16(uint32_t s, const void* g) {
    asm volatile("cp.async.cg.shared.global [%0], [%1], 16;" :: "r"(s), "l"(g));
}
#define CP_COMMIT() asm volatile("cp.async.commit_group;" ::: "memory")

__device__ __forceinline__ void ldsm4(uint32_t addr, uint32_t* r) {
    asm volatile("ldmatrix.sync.aligned.m8n8.x4.shared.b16 {%0,%1,%2,%3}, [%4];"
        : "=r"(r[0]), "=r"(r[1]), "=r"(r[2]), "=r"(r[3]) : "r"(addr));
}
// bf16 x bf16 -> f32 accum. Integer inputs => exact.
__device__ __forceinline__ void mma_bf16(float* d, const uint32_t* a, const uint32_t* b) {
    asm volatile(
        "mma.sync.aligned.m16n8k16.row.col.f32.bf16.bf16.f32 "
        "{%0,%1,%2,%3}, {%4,%5,%6,%7}, {%8,%9}, {%0,%1,%2,%3};\n"
        : "+f"(d[0]), "+f"(d[1]), "+f"(d[2]), "+f"(d[3])
        : "r"(a[0]), "r"(a[1]), "r"(a[2]), "r"(a[3]), "r"(b[0]), "r"(b[1]));
}

// 128B rows, 8x16B chunks; phys chunk = c ^ (row & 7).
__device__ __forceinline__ uint32_t swz128(int r, int c8) {
    return (uint32_t)(r * 128 + ((c8 ^ (r & 7)) << 4));
}

// ---------------- reduction helpers (templated block size) ------------------
__device__ __forceinline__ float warpSum(float v) {
#pragma unroll
    for (int o = 16; o; o >>= 1) v += __shfl_xor_sync(0xFFFFFFFFu, v, o);
    return v;
}
__device__ __forceinline__ float warpMax(float v) {
#pragma unroll
    for (int o = 16; o; o >>= 1) v = fmaxf(v, __shfl_xor_sync(0xFFFFFFFFu, v, o));
    return v;
}
template <int T>
__device__ __forceinline__ float blockSumT(float v) {
    constexpr int NWP = T / 32;
    __shared__ float red[NWP + 1];
    int warp = threadIdx.x >> 5, lane = threadIdx.x & 31;
    __syncthreads();
    v = warpSum(v);
    if (lane == 0) red[warp] = v;
    __syncthreads();
    if (warp == 0) {
        float t = (lane < NWP) ? red[lane] : 0.f;
        t = warpSum(t);
        if (lane == 0) red[NWP] = t;
    }
    __syncthreads();
    return red[NWP];
}
template <int T>
__device__ __forceinline__ float blockMaxT(float v) {
    constexpr int NWP = T / 32;
    __shared__ float redm[NWP + 1];
    int warp = threadIdx.x >> 5, lane = threadIdx.x & 31;
    __syncthreads();
    v = warpMax(v);
    if (lane == 0) redm[warp] = v;
    __syncthreads();
    if (warp == 0) {
        float t = (lane < NWP) ? redm[lane] : 0.f;
        t = warpMax(t);
        if (lane == 0) redm[NWP] = t;
    }
    __syncthreads();
    return redm[NWP];
}

// ---------------- weight abssum ---------------------------------------------
__global__ void k_abssum(const float* __restrict__ w, int n4) {
    float s = 0.f;
    const float4* w4 = (const float4*)w;
    for (int i = blockIdx.x * blockDim.x + threadIdx.x; i < n4;
         i += gridDim.x * blockDim.x) {
        float4 v = w4[i];
        s += fabsf(v.x) + fabsf(v.y) + fabsf(v.z) + fabsf(v.w);
    }
    s = warpSum(s);
    __shared__ float red[8];
    int warp = threadIdx.x >> 5, lane = threadIdx.x & 31;
    if (lane == 0) red[warp] = s;
    __syncthreads();
    if (threadIdx.x == 0) {
        float t = 0.f;
#pragma unroll
        for (int i = 0; i < 8; i++) t += red[i];
        g_part[blockIdx.x] = t;
    }
}

// ---------------- ternary weight quant (inline absmean finalize) ------------
template <int PH>
__global__ void k_quant_w(const float* __restrict__ w, int n4, float invn) {
    float ps = 0.f;
    for (int i = threadIdx.x; i < 1024; i += 256) ps += g_part[i];
    ps = blockSumT<256>(ps);
    const float s = fmaxf(ps * invn, 1e-8f);
    if (blockIdx.x == 0 && threadIdx.x == 0) {
        if (PH == 1) g_s1 = s; else g_s2 = s;
    }

    __nv_bfloat16* q = (PH == 1) ? g_w1q : g_w2q;
    const float4* w4 = (const float4*)w;
    for (int i = blockIdx.x * blockDim.x + threadIdx.x; i < n4;
         i += gridDim.x * blockDim.x) {
        float4 v = w4[i];
        __nv_bfloat162 p0, p1;
        p0.x = __float2bfloat16(fminf(1.f, fmaxf(-1.f, rintf(v.x / s))));
        p0.y = __float2bfloat16(fminf(1.f, fmaxf(-1.f, rintf(v.y / s))));
        p1.x = __float2bfloat16(fminf(1.f, fmaxf(-1.f, rintf(v.z / s))));
        p1.y = __float2bfloat16(fminf(1.f, fmaxf(-1.f, rintf(v.w / s))));
        ((__nv_bfloat162*)q)[i * 2 + 0] = p0;
        ((__nv_bfloat162*)q)[i * 2 + 1] = p1;
    }
}

// ---------------- fused LayerNorm + per-token absmax int8 quant ------------
template <int PH, int T>
__global__ void k_ln_quant(const float* __restrict__ xin) {
    constexpr int D = (PH == 1) ? D_MODEL : D_FF;
    constexpr int VPT = D / T;
    const float* in = (PH == 1) ? xin : g_h;
    __nv_bfloat16* qout = (PH == 1) ? g_xq : g_hq;
    float* fout = (PH == 1) ? g_fx : g_fh;

    const int row = blockIdx.x;
    const float4* src = (const float4*)(in + (size_t)row * D);

    float v[VPT];
#pragma unroll
    for (int k = 0; k < VPT / 4; k++) {
        float4 t = src[k * T + threadIdx.x];
        v[k * 4 + 0] = t.x; v[k * 4 + 1] = t.y;
        v[k * 4 + 2] = t.z; v[k * 4 + 3] = t.w;
    }
    float s = 0.f;
#pragma unroll
    for (int i = 0; i < VPT; i++) s += v[i];
    const float mu = blockSumT<T>(s) * (1.f / (float)D);

    float sq = 0.f, am = 0.f;
#pragma unroll
    for (int i = 0; i < VPT; i++) {
        float c = v[i] - mu;
        v[i] = c;
        sq += c * c;
        am = fmaxf(am, fabsf(c));
    }
    const float var = blockSumT<T>(sq) * (1.f / (float)D);
    const float rs = rsqrtf(var + 1e-5f);
    const float amax = blockMaxT<T>(am) * rs;
    const float qs = 127.f / fmaxf(amax, 1e-5f);

    __nv_bfloat162* dst = (__nv_bfloat162*)(qout + (size_t)row * D);
#pragma unroll
    for (int k = 0; k < VPT / 4; k++) {
        int q0, q1, q2, q3;
        float xn;
        xn = v[k * 4 + 0] * rs; q0 = (int)rintf(xn * qs);
        xn = v[k * 4 + 1] * rs; q1 = (int)rintf(xn * qs);
        xn = v[k * 4 + 2] * rs; q2 = (int)rintf(xn * qs);
        xn = v[k * 4 + 3] * rs; q3 = (int)rintf(xn * qs);
        q0 = max(-128, min(127, q0)); q1 = max(-128, min(127, q1));
        q2 = max(-128, min(127, q2)); q3 = max(-128, min(127, q3));
        __nv_bfloat162 p0, p1;
        p0.x = __float2bfloat16((float)q0); p0.y = __float2bfloat16((float)q1);
        p1.x = __float2bfloat16((float)q2); p1.y = __float2bfloat16((float)q3);
        dst[(k * T + threadIdx.x) * 2 + 0] = p0;
        dst[(k * T + threadIdx.x) * 2 + 1] = p1;
    }
    if (threadIdx.x == 0) fout[row] = fmaxf(amax, 1e-5f) * (1.f / 127.f);
}

// ---------------- bf16 GEMM: 2 CTAs/SM, BK=64, 3-stage cp.async ------------
// C[M,N] = A[M,K] (bf16 K-major) x B[N,K] (bf16 K-major), f32 accum (exact).
// CTA tile 128xBN, BK=64 (128B rows); 256 threads = 8 warps (4m x 2n),
// warp tile 32 x (BN/2). 3-stage ring, 2 CTAs resident per SM so barrier
// bubbles of one CTA are filled by the other's tensor work.
#define STG3 3
#define ASTG 16384          // 128 rows * 128B

template <int PH, int BN>
__global__ void __launch_bounds__(256, 2)
k_gemm(const float* __restrict__ bias, float* __restrict__ outp) {
    constexpr int Ng = (PH == 1) ? D_FF : D_MODEL;
    constexpr int Kg = (PH == 1) ? D_MODEL : D_FF;
    constexpr int KT = Kg / 64;
    constexpr int BSTG = BN * 128;
    constexpr int OFB = STG3 * ASTG;
    constexpr int WN = BN / 2;        // warp n-tile
    constexpr int NP = BN / 32;       // B ldsm.x4 per ks per warp (16 cols each)
    constexpr int NJ = BN / 16;       // 8-col MMA fragments per warp
    constexpr int NBC = BN / 32;      // B cp.async chunks per thread
    const __nv_bfloat16* A = (PH == 1) ? g_xq : g_hq;
    const __nv_bfloat16* B = (PH == 1) ? g_w1q : g_w2q;
    const float* fa = (PH == 1) ? g_fx : g_fh;
    const float sw = (PH == 1) ? g_s1 : g_s2;
    float* out = (PH == 1) ? g_h : outp;

    extern __shared__ char smem[];
    const uint32_t sb = smem_u32(smem);
    const int tid = threadIdx.x, lane = tid & 31, wid = tid >> 5;
    const int wm = wid & 3, wn = wid >> 2;          // 4m x 2n warps
    const int bm = blockIdx.y * 128, bn = blockIdx.x * BN;

    // ---- cp.async per-thread geometry (chunk = 16B = 8 bf16) ----
    // A stage: 1024 chunks -> 4/thread; B stage: BN*8 chunks -> NBC/thread.
    uint32_t dAo[4], dBo[NBC];
    const __nv_bfloat16 *srcA[4], *srcB[NBC];
#pragma unroll
    for (int i = 0; i < 4; i++) {
        int c = tid + i * 256, r = c >> 3, c8 = c & 7;
        dAo[i] = swz128(r, c8);
        srcA[i] = A + (size_t)(bm + r) * Kg + c8 * 8;
    }
#pragma unroll
    for (int i = 0; i < NBC; i++) {
        int c = tid + i * 256, r = c >> 3, c8 = c & 7;
        dBo[i] = swz128(r, c8);
        srcB[i] = B + (size_t)(bn + r) * Kg + c8 * 8;
    }

    // ---- ldmatrix per-lane geometry ----
    const int arow = wm * 32 + ((lane >> 3) & 1) * 8 + (lane & 7);
    const int ka = lane >> 4;                      // A k-chunk parity
    const int bcol = wn * WN + ((lane >> 4) & 1) * 8 + (lane & 7);
    const int kb = (lane >> 3) & 1;                // B k-chunk parity

    uint32_t abase[2]; int asw[2];
#pragma unroll
    for (int mi = 0; mi < 2; mi++) {
        int r = arow + mi * 16;
        abase[mi] = (uint32_t)(r * 128); asw[mi] = r & 7;
    }
    uint32_t bbase[NP]; int bsw[NP];
#pragma unroll
    for (int p = 0; p < NP; p++) {
        int r = bcol + p * 16;
        bbase[p] = (uint32_t)(r * 128); bsw[p] = r & 7;
    }

    float acc[2][NJ][4];
#pragma unroll
    for (int i = 0; i < 2; i++)
#pragma unroll
        for (int j = 0; j < NJ; j++)
#pragma unroll
            for (int r = 0; r < 4; r++) acc[i][j][r] = 0.f;

    auto load_stage = [&](int s) {
        const int buf = s % STG3;
        const size_t ko = (size_t)s * 64;           // elements
        const uint32_t sa = sb + buf * ASTG;
        const uint32_t sbB = sb + OFB + buf * BSTG;
#pragma unroll
        for (int i = 0; i < 4; i++) cp16(sa + dAo[i], srcA[i] + ko);
#pragma unroll
        for (int i = 0; i < NBC; i++) cp16(sbB + dBo[i], srcB[i] + ko);
        CP_COMMIT();
    };

    load_stage(0); load_stage(1);

    for (int kt = 0; kt < KT; kt++) {
        const int buf = kt % STG3;
        if (kt + 1 < KT) asm volatile("cp.async.wait_group 1;" ::: "memory");
        else             asm volatile("cp.async.wait_group 0;" ::: "memory");
        __syncthreads();   // stage kt ready; stage (kt-1) reads complete

        if (kt + 2 < KT) load_stage(kt + 2);   // overwrites buf (kt-1)%3: safe

        const uint32_t Ab = sb + buf * ASTG;
        const uint32_t Bb = sb + OFB + buf * BSTG;
#pragma unroll
        for (int ks = 0; ks < 4; ks++) {            // 4 x k16 per BK=64
            uint32_t a[2][4], b[NP][4];
#pragma unroll
            for (int mi = 0; mi < 2; mi++)
                ldsm4(Ab + abase[mi] + (uint32_t)((((ks << 1) | ka) ^ asw[mi]) << 4), a[mi]);
#pragma unroll
            for (int p = 0; p < NP; p++)
                ldsm4(Bb + bbase[p] + (uint32_t)((((ks << 1) | kb) ^ bsw[p]) << 4), b[p]);
#pragma unroll
            for (int mi = 0; mi < 2; mi++)
#pragma unroll
                for (int nj = 0; nj < NJ; nj++)
                    mma_bf16(acc[mi][nj], a[mi], &b[nj >> 1][(nj & 1) * 2]);
        }
    }

    // ---- epilogue: exact integer sums in f32; dequant + bias (+GELU) ----
    const int g = lane >> 2, tig = lane & 3;
#pragma unroll
    for (int mi = 0; mi < 2; mi++) {
#pragma unroll
        for (int half = 0; half < 2; half++) {
            const int row = bm + wm * 32 + mi * 16 + g + half * 8;
            const float frow = fa[row] * sw;
            float* orow = out + (size_t)row * Ng;
#pragma unroll
            for (int nj = 0; nj < NJ; nj++) {
                const int col = bn + wn * WN + nj * 8 + tig * 2;
                float2 o;
                o.x = acc[mi][nj][half * 2 + 0] * frow + bias[col + 0];
                o.y = acc[mi][nj][half * 2 + 1] * frow + bias[col + 1];
                if (PH == 1) {
                    o.x = 0.5f * o.x * (1.f + erff(o.x * 0.70710678118654752f));
                    o.y = 0.5f * o.y * (1.f + erff(o.y * 0.70710678118654752f));
                }
                *(float2*)(orow + col) = o;
            }
        }
    }
}

// ---------------- launch ----------------------------------------------------
// Launch index 3 (0-based) is what ncu captures -> GEMM1 there.
extern "C" void kernel_launch(void* const* d_in, const int* in_sizes, int n_in,
                              void* d_out, int out_size) {
    const float* x  = (const float*)d_in[0];
    const float* w1 = (const float*)d_in[1];
    const float* b1 = (const float*)d_in[2];
    const float* w2 = (const float*)d_in[3];
    const float* b2 = (const float*)d_in[4];
    float* out = (float*)d_out;

    constexpr int GS1 = STG3 * (ASTG + 128 * 128);   // 98304  (BN=128)
    constexpr int GS2 = STG3 * (ASTG + 64 * 128);    // 73728  (BN=64)
    cudaFuncSetAttribute((const void*)k_gemm<1, 128>,
                         cudaFuncAttributeMaxDynamicSharedMemorySize, GS1);
    cudaFuncSetAttribute((const void*)k_gemm<2, 64>,
                         cudaFuncAttributeMaxDynamicSharedMemorySize, GS2);

    const int n4 = (int)(NW / 4);
    const float invn = 1.f / (float)NW;

    k_ln_quant<1, 256><<<NTOK, 256>>>(x);                              // 0
    k_abssum<<<1024, 256>>>(w1, n4);                                   // 1
    k_quant_w<1><<<1024, 256>>>(w1, n4, invn);                         // 2
    k_gemm<1, 128><<<dim3(D_FF / 128, NTOK / 128), 256, GS1>>>(b1, nullptr); // 3 <- ncu
    k_abssum<<<1024, 256>>>(w2, n4);                                   // 4
    k_quant_w<2><<<1024, 256>>>(w2, n4, invn);                         // 5
    k_ln_quant<2, 512><<<NTOK, 512>>>(nullptr);                        // 6
    k_gemm<2, 64><<<dim3(D_MODEL / 64, NTOK / 128), 256, GS2>>>(b2, out);   // 7
}

// round 12
// speedup vs baseline: 1.4891x; 1.4891x over previous
#include <cuda_runtime.h>
#include <cuda_bf16.h>
#include <stdint.h>
#include <math.h>

// Problem dims (fixed by the dataset)
#define D_MODEL 2048
#define D_FF    8192
#define NTOK    8192            // B*S = 4*2048
#define NW      ((size_t)D_FF * D_MODEL)

// ---------------- scratch (device globals: allocation-free rule) -----------
__device__ __nv_bfloat16 g_w1q[D_FF * D_MODEL];   // 32 MB  ternary as bf16
__device__ __nv_bfloat16 g_w2q[D_MODEL * D_FF];   // 32 MB
__device__ __nv_bfloat16 g_xq [NTOK * D_MODEL];   // 32 MB  int8 values as bf16
__device__ __nv_bfloat16 g_hq [NTOK * D_FF];      // 128 MB
__device__ float  g_h  [NTOK * D_FF];             // 256 MB (fp32: rounding fidelity)
__device__ float  g_fx [NTOK];
__device__ float  g_fh [NTOK];
__device__ float  g_part[1024];
__device__ float  g_s1, g_s2;

// ---------------- PTX helpers (baseline ISA only: sm_80-era) ----------------
__device__ __forceinline__ uint32_t smem_u32(const void* p) {
    uint32_t a;
    asm("{ .reg .u64 t; cvta.to.shared.u64 t, %1; cvt.u32.u64 %0, t; }" : "=r"(a) : "l"(p));
    return a;
}
__device__ __forceinline__ void cp16(uint32_t s, const void* g) {
    asm volatile("cp.async.cg.shared.global [%0], [%1], 16;" :: "r"(s), "l"(g));
}
#define CP_COMMIT() asm volatile("cp.async.commit_group;" ::: "memory")

__device__ __forceinline__ void ldsm4(uint32_t addr, uint32_t* r) {
    asm volatile("ldmatrix.sync.aligned.m8n8.x4.shared.b16 {%0,%1,%2,%3}, [%4];"
        : "=r"(r[0]), "=r"(r[1]), "=r"(r[2]), "=r"(r[3]) : "r"(addr));
}
// bf16 x bf16 -> f32 accum. Integer inputs => exact.
__device__ __forceinline__ void mma_bf16(float* d, const uint32_t* a, const uint32_t* b) {
    asm volatile(
        "mma.sync.aligned.m16n8k16.row.col.f32.bf16.bf16.f32 "
        "{%0,%1,%2,%3}, {%4,%5,%6,%7}, {%8,%9}, {%0,%1,%2,%3};\n"
        : "+f"(d[0]), "+f"(d[1]), "+f"(d[2]), "+f"(d[3])
        : "r"(a[0]), "r"(a[1]), "r"(a[2]), "r"(a[3]), "r"(b[0]), "r"(b[1]));
}

// 128B rows, 8x16B chunks; phys chunk = c ^ (row & 7).
__device__ __forceinline__ uint32_t swz128(int r, int c8) {
    return (uint32_t)(r * 128 + ((c8 ^ (r & 7)) << 4));
}

// ---------------- reduction helpers (templated block size) ------------------
__device__ __forceinline__ float warpSum(float v) {
#pragma unroll
    for (int o = 16; o; o >>= 1) v += __shfl_xor_sync(0xFFFFFFFFu, v, o);
    return v;
}
__device__ __forceinline__ float warpMax(float v) {
#pragma unroll
    for (int o = 16; o; o >>= 1) v = fmaxf(v, __shfl_xor_sync(0xFFFFFFFFu, v, o));
    return v;
}
template <int T>
__device__ __forceinline__ float blockSumT(float v) {
    constexpr int NWP = T / 32;
    __shared__ float red[NWP + 1];
    int warp = threadIdx.x >> 5, lane = threadIdx.x & 31;
    __syncthreads();
    v = warpSum(v);
    if (lane == 0) red[warp] = v;
    __syncthreads();
    if (warp == 0) {
        float t = (lane < NWP) ? red[lane] : 0.f;
        t = warpSum(t);
        if (lane == 0) red[NWP] = t;
    }
    __syncthreads();
    return red[NWP];
}
template <int T>
__device__ __forceinline__ float blockMaxT(float v) {
    constexpr int NWP = T / 32;
    __shared__ float redm[NWP + 1];
    int warp = threadIdx.x >> 5, lane = threadIdx.x & 31;
    __syncthreads();
    v = warpMax(v);
    if (lane == 0) redm[warp] = v;
    __syncthreads();
    if (warp == 0) {
        float t = (lane < NWP) ? redm[lane] : 0.f;
        t = warpMax(t);
        if (lane == 0) redm[NWP] = t;
    }
    __syncthreads();
    return redm[NWP];
}

// ---------------- weight abssum ---------------------------------------------
__global__ void k_abssum(const float* __restrict__ w, int n4) {
    float s = 0.f;
    const float4* w4 = (const float4*)w;
    for (int i = blockIdx.x * blockDim.x + threadIdx.x; i < n4;
         i += gridDim.x * blockDim.x) {
        float4 v = w4[i];
        s += fabsf(v.x) + fabsf(v.y) + fabsf(v.z) + fabsf(v.w);
    }
    s = warpSum(s);
    __shared__ float red[8];
    int warp = threadIdx.x >> 5, lane = threadIdx.x & 31;
    if (lane == 0) red[warp] = s;
    __syncthreads();
    if (threadIdx.x == 0) {
        float t = 0.f;
#pragma unroll
        for (int i = 0; i < 8; i++) t += red[i];
        g_part[blockIdx.x] = t;
    }
}

// ---------------- ternary weight quant (inline absmean finalize) ------------
template <int PH>
__global__ void k_quant_w(const float* __restrict__ w, int n4, float invn) {
    float ps = 0.f;
    for (int i = threadIdx.x; i < 1024; i += 256) ps += g_part[i];
    ps = blockSumT<256>(ps);
    const float s = fmaxf(ps * invn, 1e-8f);
    if (blockIdx.x == 0 && threadIdx.x == 0) {
        if (PH == 1) g_s1 = s; else g_s2 = s;
    }

    __nv_bfloat16* q = (PH == 1) ? g_w1q : g_w2q;
    const float4* w4 = (const float4*)w;
    for (int i = blockIdx.x * blockDim.x + threadIdx.x; i < n4;
         i += gridDim.x * blockDim.x) {
        float4 v = w4[i];
        __nv_bfloat162 p0, p1;
        p0.x = __float2bfloat16(fminf(1.f, fmaxf(-1.f, rintf(v.x / s))));
        p0.y = __float2bfloat16(fminf(1.f, fmaxf(-1.f, rintf(v.y / s))));
        p1.x = __float2bfloat16(fminf(1.f, fmaxf(-1.f, rintf(v.z / s))));
        p1.y = __float2bfloat16(fminf(1.f, fmaxf(-1.f, rintf(v.w / s))));
        ((__nv_bfloat162*)q)[i * 2 + 0] = p0;
        ((__nv_bfloat162*)q)[i * 2 + 1] = p1;
    }
}

// ---------------- fused LayerNorm + per-token absmax int8 quant ------------
template <int PH, int T>
__global__ void k_ln_quant(const float* __restrict__ xin) {
    constexpr int D = (PH == 1) ? D_MODEL : D_FF;
    constexpr int VPT = D / T;
    const float* in = (PH == 1) ? xin : g_h;
    __nv_bfloat16* qout = (PH == 1) ? g_xq : g_hq;
    float* fout = (PH == 1) ? g_fx : g_fh;

    const int row = blockIdx.x;
    const float4* src = (const float4*)(in + (size_t)row * D);

    float v[VPT];
#pragma unroll
    for (int k = 0; k < VPT / 4; k++) {
        float4 t = src[k * T + threadIdx.x];
        v[k * 4 + 0] = t.x; v[k * 4 + 1] = t.y;
        v[k * 4 + 2] = t.z; v[k * 4 + 3] = t.w;
    }
    float s = 0.f;
#pragma unroll
    for (int i = 0; i < VPT; i++) s += v[i];
    const float mu = blockSumT<T>(s) * (1.f / (float)D);

    float sq = 0.f, am = 0.f;
#pragma unroll
    for (int i = 0; i < VPT; i++) {
        float c = v[i] - mu;
        v[i] = c;
        sq += c * c;
        am = fmaxf(am, fabsf(c));
    }
    const float var = blockSumT<T>(sq) * (1.f / (float)D);
    const float rs = rsqrtf(var + 1e-5f);
    const float amax = blockMaxT<T>(am) * rs;
    const float qs = 127.f / fmaxf(amax, 1e-5f);

    __nv_bfloat162* dst = (__nv_bfloat162*)(qout + (size_t)row * D);
#pragma unroll
    for (int k = 0; k < VPT / 4; k++) {
        int q0, q1, q2, q3;
        float xn;
        xn = v[k * 4 + 0] * rs; q0 = (int)rintf(xn * qs);
        xn = v[k * 4 + 1] * rs; q1 = (int)rintf(xn * qs);
        xn = v[k * 4 + 2] * rs; q2 = (int)rintf(xn * qs);
        xn = v[k * 4 + 3] * rs; q3 = (int)rintf(xn * qs);
        q0 = max(-128, min(127, q0)); q1 = max(-128, min(127, q1));
        q2 = max(-128, min(127, q2)); q3 = max(-128, min(127, q3));
        __nv_bfloat162 p0, p1;
        p0.x = __float2bfloat16((float)q0); p0.y = __float2bfloat16((float)q1);
        p1.x = __float2bfloat16((float)q2); p1.y = __float2bfloat16((float)q3);
        dst[(k * T + threadIdx.x) * 2 + 0] = p0;
        dst[(k * T + threadIdx.x) * 2 + 1] = p1;
    }
    if (threadIdx.x == 0) fout[row] = fmaxf(amax, 1e-5f) * (1.f / 127.f);
}

// ============ GEMM variant A: 256 threads, 2 CTAs/SM, 3-stage (GEMM1) =======
// CTA tile 128x128, BK=64 (128B rows); 8 warps (4m x 2n), warp tile 32x64.
#define STG3 3
#define ASTG 16384          // 128 rows * 128B

template <int PH, int BN>
__global__ void __launch_bounds__(256, 2)
k_gemm2cta(const float* __restrict__ bias, float* __restrict__ outp) {
    constexpr int Ng = (PH == 1) ? D_FF : D_MODEL;
    constexpr int Kg = (PH == 1) ? D_MODEL : D_FF;
    constexpr int KT = Kg / 64;
    constexpr int BSTG = BN * 128;
    constexpr int OFB = STG3 * ASTG;
    constexpr int WN = BN / 2;
    constexpr int NP = BN / 32;
    constexpr int NJ = BN / 16;
    constexpr int NBC = BN / 32;
    const __nv_bfloat16* A = (PH == 1) ? g_xq : g_hq;
    const __nv_bfloat16* B = (PH == 1) ? g_w1q : g_w2q;
    const float* fa = (PH == 1) ? g_fx : g_fh;
    const float sw = (PH == 1) ? g_s1 : g_s2;
    float* out = (PH == 1) ? g_h : outp;

    extern __shared__ char smem[];
    const uint32_t sb = smem_u32(smem);
    const int tid = threadIdx.x, lane = tid & 31, wid = tid >> 5;
    const int wm = wid & 3, wn = wid >> 2;
    const int bm = blockIdx.y * 128, bn = blockIdx.x * BN;

    uint32_t dAo[4], dBo[NBC];
    const __nv_bfloat16 *srcA[4], *srcB[NBC];
#pragma unroll
    for (int i = 0; i < 4; i++) {
        int c = tid + i * 256, r = c >> 3, c8 = c & 7;
        dAo[i] = swz128(r, c8);
        srcA[i] = A + (size_t)(bm + r) * Kg + c8 * 8;
    }
#pragma unroll
    for (int i = 0; i < NBC; i++) {
        int c = tid + i * 256, r = c >> 3, c8 = c & 7;
        dBo[i] = swz128(r, c8);
        srcB[i] = B + (size_t)(bn + r) * Kg + c8 * 8;
    }

    const int arow = wm * 32 + ((lane >> 3) & 1) * 8 + (lane & 7);
    const int ka = lane >> 4;
    const int bcol = wn * WN + ((lane >> 4) & 1) * 8 + (lane & 7);
    const int kb = (lane >> 3) & 1;

    uint32_t abase[2]; int asw[2];
#pragma unroll
    for (int mi = 0; mi < 2; mi++) {
        int r = arow + mi * 16;
        abase[mi] = (uint32_t)(r * 128); asw[mi] = r & 7;
    }
    uint32_t bbase[NP]; int bsw[NP];
#pragma unroll
    for (int p = 0; p < NP; p++) {
        int r = bcol + p * 16;
        bbase[p] = (uint32_t)(r * 128); bsw[p] = r & 7;
    }

    float acc[2][NJ][4];
#pragma unroll
    for (int i = 0; i < 2; i++)
#pragma unroll
        for (int j = 0; j < NJ; j++)
#pragma unroll
            for (int r = 0; r < 4; r++) acc[i][j][r] = 0.f;

    auto load_stage = [&](int s) {
        const int buf = s % STG3;
        const size_t ko = (size_t)s * 64;
        const uint32_t sa = sb + buf * ASTG;
        const uint32_t sbB = sb + OFB + buf * BSTG;
#pragma unroll
        for (int i = 0; i < 4; i++) cp16(sa + dAo[i], srcA[i] + ko);
#pragma unroll
        for (int i = 0; i < NBC; i++) cp16(sbB + dBo[i], srcB[i] + ko);
        CP_COMMIT();
    };

    load_stage(0); load_stage(1);

    for (int kt = 0; kt < KT; kt++) {
        const int buf = kt % STG3;
        if (kt + 1 < KT) asm volatile("cp.async.wait_group 1;" ::: "memory");
        else             asm volatile("cp.async.wait_group 0;" ::: "memory");
        __syncthreads();

        if (kt + 2 < KT) load_stage(kt + 2);

        const uint32_t Ab = sb + buf * ASTG;
        const uint32_t Bb = sb + OFB + buf * BSTG;
#pragma unroll
        for (int ks = 0; ks < 4; ks++) {
            uint32_t a[2][4], b[NP][4];
#pragma unroll
            for (int mi = 0; mi < 2; mi++)
                ldsm4(Ab + abase[mi] + (uint32_t)((((ks << 1) | ka) ^ asw[mi]) << 4), a[mi]);
#pragma unroll
            for (int p = 0; p < NP; p++)
                ldsm4(Bb + bbase[p] + (uint32_t)((((ks << 1) | kb) ^ bsw[p]) << 4), b[p]);
#pragma unroll
            for (int mi = 0; mi < 2; mi++)
#pragma unroll
                for (int nj = 0; nj < NJ; nj++)
                    mma_bf16(acc[mi][nj], a[mi], &b[nj >> 1][(nj & 1) * 2]);
        }
    }

    const int g = lane >> 2, tig = lane & 3;
#pragma unroll
    for (int mi = 0; mi < 2; mi++) {
#pragma unroll
        for (int half = 0; half < 2; half++) {
            const int row = bm + wm * 32 + mi * 16 + g + half * 8;
            const float frow = fa[row] * sw;
            float* orow = out + (size_t)row * Ng;
#pragma unroll
            for (int nj = 0; nj < NJ; nj++) {
                const int col = bn + wn * WN + nj * 8 + tig * 2;
                float2 o;
                o.x = acc[mi][nj][half * 2 + 0] * frow + bias[col + 0];
                o.y = acc[mi][nj][half * 2 + 1] * frow + bias[col + 1];
                if (PH == 1) {
                    o.x = 0.5f * o.x * (1.f + erff(o.x * 0.70710678118654752f));
                    o.y = 0.5f * o.y * (1.f + erff(o.y * 0.70710678118654752f));
                }
                *(float2*)(orow + col) = o;
            }
        }
    }
}

// ============ GEMM variant B: 512 threads, 1 CTA/SM, 4-stage (GEMM2) ========
// CTA tile 128xBN, BK=64; 16 warps (4m x 4n), warp tile 32 x (BN/4).
#define STG4 4
#define OFFB4 (STG4 * ASTG)   // 65536

template <int PH, int BN>
__global__ void __launch_bounds__(512, 1)
k_gemm1cta(const float* __restrict__ bias, float* __restrict__ outp) {
    constexpr int Ng = (PH == 1) ? D_FF : D_MODEL;
    constexpr int Kg = (PH == 1) ? D_MODEL : D_FF;
    constexpr int KT = Kg / 64;
    constexpr int BSTG = BN * 128;
    constexpr int WN = BN / 4;
    constexpr int NP = BN / 64;
    constexpr int NJ = BN / 32;
    constexpr int NBC = BN / 64;
    const __nv_bfloat16* A = (PH == 1) ? g_xq : g_hq;
    const __nv_bfloat16* B = (PH == 1) ? g_w1q : g_w2q;
    const float* fa = (PH == 1) ? g_fx : g_fh;
    const float sw = (PH == 1) ? g_s1 : g_s2;
    float* out = (PH == 1) ? g_h : outp;

    extern __shared__ char smem[];
    const uint32_t sb = smem_u32(smem);
    const int tid = threadIdx.x, lane = tid & 31, wid = tid >> 5;
    const int wm = wid & 3, wn = wid >> 2;
    const int bm = blockIdx.y * 128, bn = blockIdx.x * BN;

    uint32_t dAo[2], dBo[NBC];
    const __nv_bfloat16 *srcA[2], *srcB[NBC];
#pragma unroll
    for (int i = 0; i < 2; i++) {
        int c = tid + i * 512, r = c >> 3, c8 = c & 7;
        dAo[i] = swz128(r, c8);
        srcA[i] = A + (size_t)(bm + r) * Kg + c8 * 8;
    }
#pragma unroll
    for (int i = 0; i < NBC; i++) {
        int c = tid + i * 512, r = c >> 3, c8 = c & 7;
        dBo[i] = swz128(r, c8);
        srcB[i] = B + (size_t)(bn + r) * Kg + c8 * 8;
    }

    const int arow = wm * 32 + ((lane >> 3) & 1) * 8 + (lane & 7);
    const int ka = lane >> 4;
    const int bcol = wn * WN + ((lane >> 4) & 1) * 8 + (lane & 7);
    const int kb = (lane >> 3) & 1;

    uint32_t abase[2]; int asw[2];
#pragma unroll
    for (int mi = 0; mi < 2; mi++) {
        int r = arow + mi * 16;
        abase[mi] = (uint32_t)(r * 128); asw[mi] = r & 7;
    }
    uint32_t bbase[NP]; int bsw[NP];
#pragma unroll
    for (int p = 0; p < NP; p++) {
        int r = bcol + p * 16;
        bbase[p] = (uint32_t)(r * 128); bsw[p] = r & 7;
    }

    float acc[2][NJ][4];
#pragma unroll
    for (int i = 0; i < 2; i++)
#pragma unroll
        for (int j = 0; j < NJ; j++)
#pragma unroll
            for (int r = 0; r < 4; r++) acc[i][j][r] = 0.f;

    auto load_stage = [&](int s) {
        const int buf = s & (STG4 - 1);
        const size_t ko = (size_t)s * 64;
        const uint32_t sa = sb + buf * ASTG;
        const uint32_t sbB = sb + OFFB4 + buf * BSTG;
#pragma unroll
        for (int i = 0; i < 2; i++) cp16(sa + dAo[i], srcA[i] + ko);
#pragma unroll
        for (int i = 0; i < NBC; i++) cp16(sbB + dBo[i], srcB[i] + ko);
        CP_COMMIT();
    };

    load_stage(0); load_stage(1); load_stage(2);

    for (int kt = 0; kt < KT; kt++) {
        const int buf = kt & (STG4 - 1);
        const int rem = KT - 1 - kt;
        if (rem >= 2)      asm volatile("cp.async.wait_group 2;" ::: "memory");
        else if (rem == 1) asm volatile("cp.async.wait_group 1;" ::: "memory");
        else               asm volatile("cp.async.wait_group 0;" ::: "memory");
        __syncthreads();

        if (kt + 3 < KT) load_stage(kt + 3);

        const uint32_t Ab = sb + buf * ASTG;
        const uint32_t Bb = sb + OFFB4 + buf * BSTG;
#pragma unroll
        for (int ks = 0; ks < 4; ks++) {
            uint32_t a[2][4], b[NP][4];
#pragma unroll
            for (int mi = 0; mi < 2; mi++)
                ldsm4(Ab + abase[mi] + (uint32_t)((((ks << 1) | ka) ^ asw[mi]) << 4), a[mi]);
#pragma unroll
            for (int p = 0; p < NP; p++)
                ldsm4(Bb + bbase[p] + (uint32_t)((((ks << 1) | kb) ^ bsw[p]) << 4), b[p]);
#pragma unroll
            for (int mi = 0; mi < 2; mi++)
#pragma unroll
                for (int nj = 0; nj < NJ; nj++)
                    mma_bf16(acc[mi][nj], a[mi], &b[nj >> 1][(nj & 1) * 2]);
        }
    }

    const int g = lane >> 2, tig = lane & 3;
#pragma unroll
    for (int mi = 0; mi < 2; mi++) {
#pragma unroll
        for (int half = 0; half < 2; half++) {
            const int row = bm + wm * 32 + mi * 16 + g + half * 8;
            const float frow = fa[row] * sw;
            float* orow = out + (size_t)row * Ng;
#pragma unroll
            for (int nj = 0; nj < NJ; nj++) {
                const int col = bn + wn * WN + nj * 8 + tig * 2;
                float2 o;
                o.x = acc[mi][nj][half * 2 + 0] * frow + bias[col + 0];
                o.y = acc[mi][nj][half * 2 + 1] * frow + bias[col + 1];
                if (PH == 1) {
                    o.x = 0.5f * o.x * (1.f + erff(o.x * 0.70710678118654752f));
                    o.y = 0.5f * o.y * (1.f + erff(o.y * 0.70710678118654752f));
                }
                *(float2*)(orow + col) = o;
            }
        }
    }
}

// ---------------- launch ----------------------------------------------------
// Launch index 3 (0-based) is what ncu captures -> GEMM1 (2-CTA variant) there.
extern "C" void kernel_launch(void* const* d_in, const int* in_sizes, int n_in,
                              void* d_out, int out_size) {
    const float* x  = (const float*)d_in[0];
    const float* w1 = (const float*)d_in[1];
    const float* b1 = (const float*)d_in[2];
    const float* w2 = (const float*)d_in[3];
    const float* b2 = (const float*)d_in[4];
    float* out = (float*)d_out;

    constexpr int GS1 = STG3 * (ASTG + 128 * 128);   // 98304  (2 CTAs -> 192K/SM)
    constexpr int GS2 = OFFB4 + STG4 * 128 * 128;    // 131072 (1 CTA/SM)
    cudaFuncSetAttribute((const void*)k_gemm2cta<1, 128>,
                         cudaFuncAttributeMaxDynamicSharedMemorySize, GS1);
    cudaFuncSetAttribute((const void*)k_gemm1cta<2, 128>,
                         cudaFuncAttributeMaxDynamicSharedMemorySize, GS2);

    const int n4 = (int)(NW / 4);
    const float invn = 1.f / (float)NW;

    k_ln_quant<1, 256><<<NTOK, 256>>>(x);                                    // 0
    k_abssum<<<1024, 256>>>(w1, n4);                                         // 1
    k_quant_w<1><<<1024, 256>>>(w1, n4, invn);                               // 2
    k_gemm2cta<1, 128><<<dim3(D_FF / 128, NTOK / 128), 256, GS1>>>(b1, nullptr); // 3 <- ncu
    k_abssum<<<1024, 256>>>(w2, n4);                                         // 4
    k_quant_w<2><<<1024, 256>>>(w2, n4, invn);                               // 5
    k_ln_quant<2, 512><<<NTOK, 512>>>(nullptr);                              // 6
    k_gemm1cta<2, 128><<<dim3(D_MODEL / 128, NTOK / 128), 512, GS2>>>(b2, out); // 7
}

// round 13
// speedup vs baseline: 1.4954x; 1.0042x over previous
#include <cuda_runtime.h>
#include <cuda_bf16.h>
#include <stdint.h>
#include <math.h>

// Problem dims (fixed by the dataset)
#define D_MODEL 2048
#define D_FF    8192
#define NTOK    8192            // B*S = 4*2048
#define NW      ((size_t)D_FF * D_MODEL)

// ---------------- scratch (device globals: allocation-free rule) -----------
__device__ __nv_bfloat16 g_w1q[D_FF * D_MODEL];   // 32 MB  ternary as bf16
__device__ __nv_bfloat16 g_w2q[D_MODEL * D_FF];   // 32 MB
__device__ __nv_bfloat16 g_xq [NTOK * D_MODEL];   // 32 MB  int8 values as bf16
__device__ __nv_bfloat16 g_hq [NTOK * D_FF];      // 128 MB
__device__ float  g_h  [NTOK * D_FF];             // 256 MB (fp32: rounding fidelity)
__device__ float  g_fx [NTOK];
__device__ float  g_fh [NTOK];
__device__ float  g_part1[1024];
__device__ float  g_part2[1024];
__device__ float  g_s1, g_s2;

// ---------------- PTX helpers (baseline ISA only: sm_80-era) ----------------
__device__ __forceinline__ uint32_t smem_u32(const void* p) {
    uint32_t a;
    asm("{ .reg .u64 t; cvta.to.shared.u64 t, %1; cvt.u32.u64 %0, t; }" : "=r"(a) : "l"(p));
    return a;
}
__device__ __forceinline__ void cp16(uint32_t s, const void* g) {
    asm volatile("cp.async.cg.shared.global [%0], [%1], 16;" :: "r"(s), "l"(g));
}
#define CP_COMMIT() asm volatile("cp.async.commit_group;" ::: "memory")

__device__ __forceinline__ void ldsm4(uint32_t addr, uint32_t* r) {
    asm volatile("ldmatrix.sync.aligned.m8n8.x4.shared.b16 {%0,%1,%2,%3}, [%4];"
        : "=r"(r[0]), "=r"(r[1]), "=r"(r[2]), "=r"(r[3]) : "r"(addr));
}
// bf16 x bf16 -> f32 accum. Integer inputs => exact.
__device__ __forceinline__ void mma_bf16(float* d, const uint32_t* a, const uint32_t* b) {
    asm volatile(
        "mma.sync.aligned.m16n8k16.row.col.f32.bf16.bf16.f32 "
        "{%0,%1,%2,%3}, {%4,%5,%6,%7}, {%8,%9}, {%0,%1,%2,%3};\n"
        : "+f"(d[0]), "+f"(d[1]), "+f"(d[2]), "+f"(d[3])
        : "r"(a[0]), "r"(a[1]), "r"(a[2]), "r"(a[3]), "r"(b[0]), "r"(b[1]));
}

// 128B rows, 8x16B chunks; phys chunk = c ^ (row & 7).
__device__ __forceinline__ uint32_t swz128(int r, int c8) {
    return (uint32_t)(r * 128 + ((c8 ^ (r & 7)) << 4));
}

// ---------------- reduction helpers (templated block size) ------------------
__device__ __forceinline__ float warpSum(float v) {
#pragma unroll
    for (int o = 16; o; o >>= 1) v += __shfl_xor_sync(0xFFFFFFFFu, v, o);
    return v;
}
__device__ __forceinline__ float warpMax(float v) {
#pragma unroll
    for (int o = 16; o; o >>= 1) v = fmaxf(v, __shfl_xor_sync(0xFFFFFFFFu, v, o));
    return v;
}
template <int T>
__device__ __forceinline__ float blockSumT(float v) {
    constexpr int NWP = T / 32;
    __shared__ float red[NWP + 1];
    int warp = threadIdx.x >> 5, lane = threadIdx.x & 31;
    __syncthreads();
    v = warpSum(v);
    if (lane == 0) red[warp] = v;
    __syncthreads();
    if (warp == 0) {
        float t = (lane < NWP) ? red[lane] : 0.f;
        t = warpSum(t);
        if (lane == 0) red[NWP] = t;
    }
    __syncthreads();
    return red[NWP];
}
template <int T>
__device__ __forceinline__ float blockMaxT(float v) {
    constexpr int NWP = T / 32;
    __shared__ float redm[NWP + 1];
    int warp = threadIdx.x >> 5, lane = threadIdx.x & 31;
    __syncthreads();
    v = warpMax(v);
    if (lane == 0) redm[warp] = v;
    __syncthreads();
    if (warp == 0) {
        float t = (lane < NWP) ? redm[lane] : 0.f;
        t = warpMax(t);
        if (lane == 0) redm[NWP] = t;
    }
    __syncthreads();
    return redm[NWP];
}

// ---------------- device bodies (for fused heterogeneous kernels) -----------
// abssum over one weight matrix; 256-thread blocks, vbid in [0,1024).
template <int T>
__device__ __forceinline__ void d_abssum(const float* __restrict__ w, int n4,
                                         int vbid, float* part) {
    float s = 0.f;
    const float4* w4 = (const float4*)w;
    for (int i = vbid * T + threadIdx.x; i < n4; i += 1024 * T) {
        float4 v = w4[i];
        s += fabsf(v.x) + fabsf(v.y) + fabsf(v.z) + fabsf(v.w);
    }
    s = blockSumT<T>(s);
    if (threadIdx.x == 0) part[vbid] = s;
}

// ternary quant with inline absmean finalize; all blocks recompute the same
// scalar with the identical tree (bit-identical); vbid 0 publishes it.
template <int PH, int T>
__device__ __forceinline__ void d_quant_w(const float* __restrict__ w, int n4,
                                          float invn, int vbid,
                                          const float* part) {
    float ps = 0.f;
    for (int i = threadIdx.x; i < 1024; i += T) ps += part[i];
    ps = blockSumT<T>(ps);
    const float s = fmaxf(ps * invn, 1e-8f);
    if (vbid == 0 && threadIdx.x == 0) {
        if (PH == 1) g_s1 = s; else g_s2 = s;
    }

    __nv_bfloat16* q = (PH == 1) ? g_w1q : g_w2q;
    const float4* w4 = (const float4*)w;
    for (int i = vbid * T + threadIdx.x; i < n4; i += 1024 * T) {
        float4 v = w4[i];
        __nv_bfloat162 p0, p1;
        p0.x = __float2bfloat16(fminf(1.f, fmaxf(-1.f, rintf(v.x / s))));
        p0.y = __float2bfloat16(fminf(1.f, fmaxf(-1.f, rintf(v.y / s))));
        p1.x = __float2bfloat16(fminf(1.f, fmaxf(-1.f, rintf(v.z / s))));
        p1.y = __float2bfloat16(fminf(1.f, fmaxf(-1.f, rintf(v.w / s))));
        ((__nv_bfloat162*)q)[i * 2 + 0] = p0;
        ((__nv_bfloat162*)q)[i * 2 + 1] = p1;
    }
}

// fused LayerNorm + per-token absmax int8 quant (values staged as bf16)
template <int PH, int T>
__device__ __forceinline__ void d_ln_quant(const float* __restrict__ in, int row) {
    constexpr int D = (PH == 1) ? D_MODEL : D_FF;
    constexpr int VPT = D / T;
    __nv_bfloat16* qout = (PH == 1) ? g_xq : g_hq;
    float* fout = (PH == 1) ? g_fx : g_fh;

    const float4* src = (const float4*)(in + (size_t)row * D);

    float v[VPT];
#pragma unroll
    for (int k = 0; k < VPT / 4; k++) {
        float4 t = src[k * T + threadIdx.x];
        v[k * 4 + 0] = t.x; v[k * 4 + 1] = t.y;
        v[k * 4 + 2] = t.z; v[k * 4 + 3] = t.w;
    }
    float s = 0.f;
#pragma unroll
    for (int i = 0; i < VPT; i++) s += v[i];
    const float mu = blockSumT<T>(s) * (1.f / (float)D);

    float sq = 0.f, am = 0.f;
#pragma unroll
    for (int i = 0; i < VPT; i++) {
        float c = v[i] - mu;
        v[i] = c;
        sq += c * c;
        am = fmaxf(am, fabsf(c));
    }
    const float var = blockSumT<T>(sq) * (1.f / (float)D);
    const float rs = rsqrtf(var + 1e-5f);
    const float amax = blockMaxT<T>(am) * rs;
    const float qs = 127.f / fmaxf(amax, 1e-5f);

    __nv_bfloat162* dst = (__nv_bfloat162*)(qout + (size_t)row * D);
#pragma unroll
    for (int k = 0; k < VPT / 4; k++) {
        int q0, q1, q2, q3;
        float xn;
        xn = v[k * 4 + 0] * rs; q0 = (int)rintf(xn * qs);
        xn = v[k * 4 + 1] * rs; q1 = (int)rintf(xn * qs);
        xn = v[k * 4 + 2] * rs; q2 = (int)rintf(xn * qs);
        xn = v[k * 4 + 3] * rs; q3 = (int)rintf(xn * qs);
        q0 = max(-128, min(127, q0)); q1 = max(-128, min(127, q1));
        q2 = max(-128, min(127, q2)); q3 = max(-128, min(127, q3));
        __nv_bfloat162 p0, p1;
        p0.x = __float2bfloat16((float)q0); p0.y = __float2bfloat16((float)q1);
        p1.x = __float2bfloat16((float)q2); p1.y = __float2bfloat16((float)q3);
        dst[(k * T + threadIdx.x) * 2 + 0] = p0;
        dst[(k * T + threadIdx.x) * 2 + 1] = p1;
    }
    if (threadIdx.x == 0) fout[row] = fmaxf(amax, 1e-5f) * (1.f / 127.f);
}

// ---------------- fused prep kernels (heterogeneous block roles) -----------
// K1: blocks [0,8192) = ln_quant1 rows; [8192,9216) = abssum(w1) -> g_part1
__global__ void __launch_bounds__(256)
k_fused1(const float* __restrict__ x, const float* __restrict__ w1, int n4) {
    if (blockIdx.x < NTOK) d_ln_quant<1, 256>(x, blockIdx.x);
    else                   d_abssum<256>(w1, n4, blockIdx.x - NTOK, g_part1);
}

// K2: blocks [0,1024) = quant_w1 (reads g_part1); [1024,2048) = abssum(w2)
__global__ void __launch_bounds__(256)
k_fused2(const float* __restrict__ w1, const float* __restrict__ w2,
         int n4, float invn) {
    if (blockIdx.x < 1024) d_quant_w<1, 256>(w1, n4, invn, blockIdx.x, g_part1);
    else                   d_abssum<256>(w2, n4, blockIdx.x - 1024, g_part2);
}

// K3: blocks [0,8192) = ln_quant2 rows; [8192,9216) = quant_w2 (g_part2)
__global__ void __launch_bounds__(512)
k_fused3(const float* __restrict__ w2, int n4, float invn) {
    if (blockIdx.x < NTOK) d_ln_quant<2, 512>(g_h, blockIdx.x);
    else                   d_quant_w<2, 512>(w2, n4, invn, blockIdx.x - NTOK, g_part2);
}

// ============ GEMM variant A: 256 threads, 2 CTAs/SM, 3-stage (GEMM1) =======
// CTA tile 128x128, BK=64 (128B rows); 8 warps (4m x 2n), warp tile 32x64.
#define STG3 3
#define ASTG 16384          // 128 rows * 128B

template <int PH, int BN>
__global__ void __launch_bounds__(256, 2)
k_gemm2cta(const float* __restrict__ bias, float* __restrict__ outp) {
    constexpr int Ng = (PH == 1) ? D_FF : D_MODEL;
    constexpr int Kg = (PH == 1) ? D_MODEL : D_FF;
    constexpr int KT = Kg / 64;
    constexpr int BSTG = BN * 128;
    constexpr int OFB = STG3 * ASTG;
    constexpr int WN = BN / 2;
    constexpr int NP = BN / 32;
    constexpr int NJ = BN / 16;
    constexpr int NBC = BN / 32;
    const __nv_bfloat16* A = (PH == 1) ? g_xq : g_hq;
    const __nv_bfloat16* B = (PH == 1) ? g_w1q : g_w2q;
    const float* fa = (PH == 1) ? g_fx : g_fh;
    const float sw = (PH == 1) ? g_s1 : g_s2;
    float* out = (PH == 1) ? g_h : outp;

    extern __shared__ char smem[];
    const uint32_t sb = smem_u32(smem);
    const int tid = threadIdx.x, lane = tid & 31, wid = tid >> 5;
    const int wm = wid & 3, wn = wid >> 2;
    const int bm = blockIdx.y * 128, bn = blockIdx.x * BN;

    uint32_t dAo[4], dBo[NBC];
    const __nv_bfloat16 *srcA[4], *srcB[NBC];
#pragma unroll
    for (int i = 0; i < 4; i++) {
        int c = tid + i * 256, r = c >> 3, c8 = c & 7;
        dAo[i] = swz128(r, c8);
        srcA[i] = A + (size_t)(bm + r) * Kg + c8 * 8;
    }
#pragma unroll
    for (int i = 0; i < NBC; i++) {
        int c = tid + i * 256, r = c >> 3, c8 = c & 7;
        dBo[i] = swz128(r, c8);
        srcB[i] = B + (size_t)(bn + r) * Kg + c8 * 8;
    }

    const int arow = wm * 32 + ((lane >> 3) & 1) * 8 + (lane & 7);
    const int ka = lane >> 4;
    const int bcol = wn * WN + ((lane >> 4) & 1) * 8 + (lane & 7);
    const int kb = (lane >> 3) & 1;

    uint32_t abase[2]; int asw[2];
#pragma unroll
    for (int mi = 0; mi < 2; mi++) {
        int r = arow + mi * 16;
        abase[mi] = (uint32_t)(r * 128); asw[mi] = r & 7;
    }
    uint32_t bbase[NP]; int bsw[NP];
#pragma unroll
    for (int p = 0; p < NP; p++) {
        int r = bcol + p * 16;
        bbase[p] = (uint32_t)(r * 128); bsw[p] = r & 7;
    }

    float acc[2][NJ][4];
#pragma unroll
    for (int i = 0; i < 2; i++)
#pragma unroll
        for (int j = 0; j < NJ; j++)
#pragma unroll
            for (int r = 0; r < 4; r++) acc[i][j][r] = 0.f;

    auto load_stage = [&](int s) {
        const int buf = s % STG3;
        const size_t ko = (size_t)s * 64;
        const uint32_t sa = sb + buf * ASTG;
        const uint32_t sbB = sb + OFB + buf * BSTG;
#pragma unroll
        for (int i = 0; i < 4; i++) cp16(sa + dAo[i], srcA[i] + ko);
#pragma unroll
        for (int i = 0; i < NBC; i++) cp16(sbB + dBo[i], srcB[i] + ko);
        CP_COMMIT();
    };

    load_stage(0); load_stage(1);

    for (int kt = 0; kt < KT; kt++) {
        const int buf = kt % STG3;
        if (kt + 1 < KT) asm volatile("cp.async.wait_group 1;" ::: "memory");
        else             asm volatile("cp.async.wait_group 0;" ::: "memory");
        __syncthreads();

        if (kt + 2 < KT) load_stage(kt + 2);

        const uint32_t Ab = sb + buf * ASTG;
        const uint32_t Bb = sb + OFB + buf * BSTG;
#pragma unroll
        for (int ks = 0; ks < 4; ks++) {
            uint32_t a[2][4], b[NP][4];
#pragma unroll
            for (int mi = 0; mi < 2; mi++)
                ldsm4(Ab + abase[mi] + (uint32_t)((((ks << 1) | ka) ^ asw[mi]) << 4), a[mi]);
#pragma unroll
            for (int p = 0; p < NP; p++)
                ldsm4(Bb + bbase[p] + (uint32_t)((((ks << 1) | kb) ^ bsw[p]) << 4), b[p]);
#pragma unroll
            for (int mi = 0; mi < 2; mi++)
#pragma unroll
                for (int nj = 0; nj < NJ; nj++)
                    mma_bf16(acc[mi][nj], a[mi], &b[nj >> 1][(nj & 1) * 2]);
        }
    }

    const int g = lane >> 2, tig = lane & 3;
#pragma unroll
    for (int mi = 0; mi < 2; mi++) {
#pragma unroll
        for (int half = 0; half < 2; half++) {
            const int row = bm + wm * 32 + mi * 16 + g + half * 8;
            const float frow = fa[row] * sw;
            float* orow = out + (size_t)row * Ng;
#pragma unroll
            for (int nj = 0; nj < NJ; nj++) {
                const int col = bn + wn * WN + nj * 8 + tig * 2;
                float2 o;
                o.x = acc[mi][nj][half * 2 + 0] * frow + bias[col + 0];
                o.y = acc[mi][nj][half * 2 + 1] * frow + bias[col + 1];
                if (PH == 1) {
                    o.x = 0.5f * o.x * (1.f + erff(o.x * 0.70710678118654752f));
                    o.y = 0.5f * o.y * (1.f + erff(o.y * 0.70710678118654752f));
                }
                *(float2*)(orow + col) = o;
            }
        }
    }
}

// ============ GEMM variant B: 512 threads, 1 CTA/SM, 4-stage (GEMM2) ========
// CTA tile 128xBN, BK=64; 16 warps (4m x 4n), warp tile 32 x (BN/4).
#define STG4 4
#define OFFB4 (STG4 * ASTG)   // 65536

template <int PH, int BN>
__global__ void __launch_bounds__(512, 1)
k_gemm1cta(const float* __restrict__ bias, float* __restrict__ outp) {
    constexpr int Ng = (PH == 1) ? D_FF : D_MODEL;
    constexpr int Kg = (PH == 1) ? D_MODEL : D_FF;
    constexpr int KT = Kg / 64;
    constexpr int BSTG = BN * 128;
    constexpr int WN = BN / 4;
    constexpr int NP = BN / 64;
    constexpr int NJ = BN / 32;
    constexpr int NBC = BN / 64;
    const __nv_bfloat16* A = (PH == 1) ? g_xq : g_hq;
    const __nv_bfloat16* B = (PH == 1) ? g_w1q : g_w2q;
    const float* fa = (PH == 1) ? g_fx : g_fh;
    const float sw = (PH == 1) ? g_s1 : g_s2;
    float* out = (PH == 1) ? g_h : outp;

    extern __shared__ char smem[];
    const uint32_t sb = smem_u32(smem);
    const int tid = threadIdx.x, lane = tid & 31, wid = tid >> 5;
    const int wm = wid & 3, wn = wid >> 2;
    const int bm = blockIdx.y * 128, bn = blockIdx.x * BN;

    uint32_t dAo[2], dBo[NBC];
    const __nv_bfloat16 *srcA[2], *srcB[NBC];
#pragma unroll
    for (int i = 0; i < 2; i++) {
        int c = tid + i * 512, r = c >> 3, c8 = c & 7;
        dAo[i] = swz128(r, c8);
        srcA[i] = A + (size_t)(bm + r) * Kg + c8 * 8;
    }
#pragma unroll
    for (int i = 0; i < NBC; i++) {
        int c = tid + i * 512, r = c >> 3, c8 = c & 7;
        dBo[i] = swz128(r, c8);
        srcB[i] = B + (size_t)(bn + r) * Kg + c8 * 8;
    }

    const int arow = wm * 32 + ((lane >> 3) & 1) * 8 + (lane & 7);
    const int ka = lane >> 4;
    const int bcol = wn * WN + ((lane >> 4) & 1) * 8 + (lane & 7);
    const int kb = (lane >> 3) & 1;

    uint32_t abase[2]; int asw[2];
#pragma unroll
    for (int mi = 0; mi < 2; mi++) {
        int r = arow + mi * 16;
        abase[mi] = (uint32_t)(r * 128); asw[mi] = r & 7;
    }
    uint32_t bbase[NP]; int bsw[NP];
#pragma unroll
    for (int p = 0; p < NP; p++) {
        int r = bcol + p * 16;
        bbase[p] = (uint32_t)(r * 128); bsw[p] = r & 7;
    }

    float acc[2][NJ][4];
#pragma unroll
    for (int i = 0; i < 2; i++)
#pragma unroll
        for (int j = 0; j < NJ; j++)
#pragma unroll
            for (int r = 0; r < 4; r++) acc[i][j][r] = 0.f;

    auto load_stage = [&](int s) {
        const int buf = s & (STG4 - 1);
        const size_t ko = (size_t)s * 64;
        const uint32_t sa = sb + buf * ASTG;
        const uint32_t sbB = sb + OFFB4 + buf * BSTG;
#pragma unroll
        for (int i = 0; i < 2; i++) cp16(sa + dAo[i], srcA[i] + ko);
#pragma unroll
        for (int i = 0; i < NBC; i++) cp16(sbB + dBo[i], srcB[i] + ko);
        CP_COMMIT();
    };

    load_stage(0); load_stage(1); load_stage(2);

    for (int kt = 0; kt < KT; kt++) {
        const int buf = kt & (STG4 - 1);
        const int rem = KT - 1 - kt;
        if (rem >= 2)      asm volatile("cp.async.wait_group 2;" ::: "memory");
        else if (rem == 1) asm volatile("cp.async.wait_group 1;" ::: "memory");
        else               asm volatile("cp.async.wait_group 0;" ::: "memory");
        __syncthreads();

        if (kt + 3 < KT) load_stage(kt + 3);

        const uint32_t Ab = sb + buf * ASTG;
        const uint32_t Bb = sb + OFFB4 + buf * BSTG;
#pragma unroll
        for (int ks = 0; ks < 4; ks++) {
            uint32_t a[2][4], b[NP][4];
#pragma unroll
            for (int mi = 0; mi < 2; mi++)
                ldsm4(Ab + abase[mi] + (uint32_t)((((ks << 1) | ka) ^ asw[mi]) << 4), a[mi]);
#pragma unroll
            for (int p = 0; p < NP; p++)
                ldsm4(Bb + bbase[p] + (uint32_t)((((ks << 1) | kb) ^ bsw[p]) << 4), b[p]);
#pragma unroll
            for (int mi = 0; mi < 2; mi++)
#pragma unroll
                for (int nj = 0; nj < NJ; nj++)
                    mma_bf16(acc[mi][nj], a[mi], &b[nj >> 1][(nj & 1) * 2]);
        }
    }

    const int g = lane >> 2, tig = lane & 3;
#pragma unroll
    for (int mi = 0; mi < 2; mi++) {
#pragma unroll
        for (int half = 0; half < 2; half++) {
            const int row = bm + wm * 32 + mi * 16 + g + half * 8;
            const float frow = fa[row] * sw;
            float* orow = out + (size_t)row * Ng;
#pragma unroll
            for (int nj = 0; nj < NJ; nj++) {
                const int col = bn + wn * WN + nj * 8 + tig * 2;
                float2 o;
                o.x = acc[mi][nj][half * 2 + 0] * frow + bias[col + 0];
                o.y = acc[mi][nj][half * 2 + 1] * frow + bias[col + 1];
                if (PH == 1) {
                    o.x = 0.5f * o.x * (1.f + erff(o.x * 0.70710678118654752f));
                    o.y = 0.5f * o.y * (1.f + erff(o.y * 0.70710678118654752f));
                }
                *(float2*)(orow + col) = o;
            }
        }
    }
}

// ---------------- launch ----------------------------------------------------
// Sequence: K1, K2, GEMM1, K3, GEMM2.  ncu (0-based idx 3) captures K3.
extern "C" void kernel_launch(void* const* d_in, const int* in_sizes, int n_in,
                              void* d_out, int out_size) {
    const float* x  = (const float*)d_in[0];
    const float* w1 = (const float*)d_in[1];
    const float* b1 = (const float*)d_in[2];
    const float* w2 = (const float*)d_in[3];
    const float* b2 = (const float*)d_in[4];
    float* out = (float*)d_out;

    constexpr int GS1 = STG3 * (ASTG + 128 * 128);   // 98304  (2 CTAs -> 192K/SM)
    constexpr int GS2 = OFFB4 + STG4 * 128 * 128;    // 131072 (1 CTA/SM)
    cudaFuncSetAttribute((const void*)k_gemm2cta<1, 128>,
                         cudaFuncAttributeMaxDynamicSharedMemorySize, GS1);
    cudaFuncSetAttribute((const void*)k_gemm1cta<2, 128>,
                         cudaFuncAttributeMaxDynamicSharedMemorySize, GS2);

    const int n4 = (int)(NW / 4);
    const float invn = 1.f / (float)NW;

    k_fused1<<<NTOK + 1024, 256>>>(x, w1, n4);                               // 0
    k_fused2<<<2048, 256>>>(w1, w2, n4, invn);                               // 1
    k_gemm2cta<1, 128><<<dim3(D_FF / 128, NTOK / 128), 256, GS1>>>(b1, nullptr); // 2
    k_fused3<<<NTOK + 1024, 512>>>(w2, n4, invn);                            // 3 <- ncu
    k_gemm1cta<2, 128><<<dim3(D_MODEL / 128, NTOK / 128), 512, GS2>>>(b2, out); // 4
}

// round 15
// speedup vs baseline: 1.6084x; 1.0756x over previous
#include <cuda_runtime.h>
#include <cuda_bf16.h>
#include <stdint.h>
#include <math.h>

// Problem dims (fixed by the dataset)
#define D_MODEL 2048
#define D_FF    8192
#define NTOK    8192            // B*S = 4*2048
#define NW      ((size_t)D_FF * D_MODEL)

// ---------------- scratch (device globals: allocation-free rule) -----------
__device__ __nv_bfloat16 g_w1q[D_FF * D_MODEL];   // 32 MB  ternary as bf16
__device__ __nv_bfloat16 g_w2q[D_MODEL * D_FF];   // 32 MB
__device__ __nv_bfloat16 g_xq [NTOK * D_MODEL];   // 32 MB  int8 values as bf16
__device__ __nv_bfloat16 g_hq [NTOK * D_FF];      // 128 MB
__device__ float  g_h  [NTOK * D_FF];             // 256 MB; h (fp32) for K3, then
                                                  // reused as split-K partials
__device__ float  g_fx [NTOK];
__device__ float  g_fh [NTOK];
__device__ float  g_part1[1024];
__device__ float  g_part2[1024];
__device__ float  g_s1, g_s2;

// ---------------- PTX helpers (baseline ISA only: sm_80-era) ----------------
__device__ __forceinline__ uint32_t smem_u32(const void* p) {
    uint32_t a;
    asm("{ .reg .u64 t; cvta.to.shared.u64 t, %1; cvt.u32.u64 %0, t; }" : "=r"(a) : "l"(p));
    return a;
}
__device__ __forceinline__ void cp16(uint32_t s, const void* g) {
    asm volatile("cp.async.cg.shared.global [%0], [%1], 16;" :: "r"(s), "l"(g));
}
#define CP_COMMIT() asm volatile("cp.async.commit_group;" ::: "memory")

__device__ __forceinline__ void ldsm4(uint32_t addr, uint32_t* r) {
    asm volatile("ldmatrix.sync.aligned.m8n8.x4.shared.b16 {%0,%1,%2,%3}, [%4];"
        : "=r"(r[0]), "=r"(r[1]), "=r"(r[2]), "=r"(r[3]) : "r"(addr));
}
// bf16 x bf16 -> f32 accum. Integer inputs => exact.
__device__ __forceinline__ void mma_bf16(float* d, const uint32_t* a, const uint32_t* b) {
    asm volatile(
        "mma.sync.aligned.m16n8k16.row.col.f32.bf16.bf16.f32 "
        "{%0,%1,%2,%3}, {%4,%5,%6,%7}, {%8,%9}, {%0,%1,%2,%3};\n"
        : "+f"(d[0]), "+f"(d[1]), "+f"(d[2]), "+f"(d[3])
        : "r"(a[0]), "r"(a[1]), "r"(a[2]), "r"(a[3]), "r"(b[0]), "r"(b[1]));
}

// 128B rows, 8x16B chunks; phys chunk = c ^ (row & 7).
__device__ __forceinline__ uint32_t swz128(int r, int c8) {
    return (uint32_t)(r * 128 + ((c8 ^ (r & 7)) << 4));
}

// ---------------- reduction helpers (templated block size) ------------------
__device__ __forceinline__ float warpSum(float v) {
#pragma unroll
    for (int o = 16; o; o >>= 1) v += __shfl_xor_sync(0xFFFFFFFFu, v, o);
    return v;
}
__device__ __forceinline__ float warpMax(float v) {
#pragma unroll
    for (int o = 16; o; o >>= 1) v = fmaxf(v, __shfl_xor_sync(0xFFFFFFFFu, v, o));
    return v;
}
template <int T>
__device__ __forceinline__ float blockSumT(float v) {
    constexpr int NWP = T / 32;
    __shared__ float red[NWP + 1];
    int warp = threadIdx.x >> 5, lane = threadIdx.x & 31;
    __syncthreads();
    v = warpSum(v);
    if (lane == 0) red[warp] = v;
    __syncthreads();
    if (warp == 0) {
        float t = (lane < NWP) ? red[lane] : 0.f;
        t = warpSum(t);
        if (lane == 0) red[NWP] = t;
    }
    __syncthreads();
    return red[NWP];
}
template <int T>
__device__ __forceinline__ float blockMaxT(float v) {
    constexpr int NWP = T / 32;
    __shared__ float redm[NWP + 1];
    int warp = threadIdx.x >> 5, lane = threadIdx.x & 31;
    __syncthreads();
    v = warpMax(v);
    if (lane == 0) redm[warp] = v;
    __syncthreads();
    if (warp == 0) {
        float t = (lane < NWP) ? redm[lane] : 0.f;
        t = warpMax(t);
        if (lane == 0) redm[NWP] = t;
    }
    __syncthreads();
    return redm[NWP];
}

// ---------------- device bodies (for fused heterogeneous kernels) -----------
template <int T>
__device__ __forceinline__ void d_abssum(const float* __restrict__ w, int n4,
                                         int vbid, float* part) {
    float s = 0.f;
    const float4* w4 = (const float4*)w;
    for (int i = vbid * T + threadIdx.x; i < n4; i += 1024 * T) {
        float4 v = w4[i];
        s += fabsf(v.x) + fabsf(v.y) + fabsf(v.z) + fabsf(v.w);
    }
    s = blockSumT<T>(s);
    if (threadIdx.x == 0) part[vbid] = s;
}

template <int PH, int T>
__device__ __forceinline__ void d_quant_w(const float* __restrict__ w, int n4,
                                          float invn, int vbid,
                                          const float* part) {
    float ps = 0.f;
    for (int i = threadIdx.x; i < 1024; i += T) ps += part[i];
    ps = blockSumT<T>(ps);
    const float s = fmaxf(ps * invn, 1e-8f);
    if (vbid == 0 && threadIdx.x == 0) {
        if (PH == 1) g_s1 = s; else g_s2 = s;
    }

    __nv_bfloat16* q = (PH == 1) ? g_w1q : g_w2q;
    const float4* w4 = (const float4*)w;
    for (int i = vbid * T + threadIdx.x; i < n4; i += 1024 * T) {
        float4 v = w4[i];
        __nv_bfloat162 p0, p1;
        p0.x = __float2bfloat16(fminf(1.f, fmaxf(-1.f, rintf(v.x / s))));
        p0.y = __float2bfloat16(fminf(1.f, fmaxf(-1.f, rintf(v.y / s))));
        p1.x = __float2bfloat16(fminf(1.f, fmaxf(-1.f, rintf(v.z / s))));
        p1.y = __float2bfloat16(fminf(1.f, fmaxf(-1.f, rintf(v.w / s))));
        ((__nv_bfloat162*)q)[i * 2 + 0] = p0;
        ((__nv_bfloat162*)q)[i * 2 + 1] = p1;
    }
}

template <int PH, int T>
__device__ __forceinline__ void d_ln_quant(const float* __restrict__ in, int row) {
    constexpr int D = (PH == 1) ? D_MODEL : D_FF;
    constexpr int VPT = D / T;
    __nv_bfloat16* qout = (PH == 1) ? g_xq : g_hq;
    float* fout = (PH == 1) ? g_fx : g_fh;

    const float4* src = (const float4*)(in + (size_t)row * D);

    float v[VPT];
#pragma unroll
    for (int k = 0; k < VPT / 4; k++) {
        float4 t = src[k * T + threadIdx.x];
        v[k * 4 + 0] = t.x; v[k * 4 + 1] = t.y;
        v[k * 4 + 2] = t.z; v[k * 4 + 3] = t.w;
    }
    float s = 0.f;
#pragma unroll
    for (int i = 0; i < VPT; i++) s += v[i];
    const float mu = blockSumT<T>(s) * (1.f / (float)D);

    float sq = 0.f, am = 0.f;
#pragma unroll
    for (int i = 0; i < VPT; i++) {
        float c = v[i] - mu;
        v[i] = c;
        sq += c * c;
        am = fmaxf(am, fabsf(c));
    }
    const float var = blockSumT<T>(sq) * (1.f / (float)D);
    const float rs = rsqrtf(var + 1e-5f);
    const float amax = blockMaxT<T>(am) * rs;
    const float qs = 127.f / fmaxf(amax, 1e-5f);

    __nv_bfloat162* dst = (__nv_bfloat162*)(qout + (size_t)row * D);
#pragma unroll
    for (int k = 0; k < VPT / 4; k++) {
        int q0, q1, q2, q3;
        float xn;
        xn = v[k * 4 + 0] * rs; q0 = (int)rintf(xn * qs);
        xn = v[k * 4 + 1] * rs; q1 = (int)rintf(xn * qs);
        xn = v[k * 4 + 2] * rs; q2 = (int)rintf(xn * qs);
        xn = v[k * 4 + 3] * rs; q3 = (int)rintf(xn * qs);
        q0 = max(-128, min(127, q0)); q1 = max(-128, min(127, q1));
        q2 = max(-128, min(127, q2)); q3 = max(-128, min(127, q3));
        __nv_bfloat162 p0, p1;
        p0.x = __float2bfloat16((float)q0); p0.y = __float2bfloat16((float)q1);
        p1.x = __float2bfloat16((float)q2); p1.y = __float2bfloat16((float)q3);
        dst[(k * T + threadIdx.x) * 2 + 0] = p0;
        dst[(k * T + threadIdx.x) * 2 + 1] = p1;
    }
    if (threadIdx.x == 0) fout[row] = fmaxf(amax, 1e-5f) * (1.f / 127.f);
}

// ---------------- fused prep kernels (heterogeneous block roles) -----------
__global__ void __launch_bounds__(256)
k_fused1(const float* __restrict__ x, const float* __restrict__ w1, int n4) {
    if (blockIdx.x < NTOK) d_ln_quant<1, 256>(x, blockIdx.x);
    else                   d_abssum<256>(w1, n4, blockIdx.x - NTOK, g_part1);
}

__global__ void __launch_bounds__(256)
k_fused2(const float* __restrict__ w1, const float* __restrict__ w2,
         int n4, float invn) {
    if (blockIdx.x < 1024) d_quant_w<1, 256>(w1, n4, invn, blockIdx.x, g_part1);
    else                   d_abssum<256>(w2, n4, blockIdx.x - 1024, g_part2);
}

__global__ void __launch_bounds__(512)
k_fused3(const float* __restrict__ w2, int n4, float invn) {
    if (blockIdx.x < NTOK) d_ln_quant<2, 512>(g_h, blockIdx.x);
    else                   d_quant_w<2, 512>(w2, n4, invn, blockIdx.x - NTOK, g_part2);
}

// ============ GEMM: 256 threads, 2 CTAs/SM, 3-stage, optional split-K =======
// CTA tile 128x128, BK=64 (128B rows); 8 warps (4m x 2n), warp tile 32x64.
// SK=1: full K, fused dequant+bias(+GELU) epilogue.
// SK=2: K halved per CTA (blockIdx.z selects half); raw f32 integer partial
//       sums stored to g_h (dead after K3); k_reduce finalizes.
#define STG3 3
#define ASTG 16384          // 128 rows * 128B

template <int PH, int BN, int SK>
__global__ void __launch_bounds__(256, 2)
k_gemm2cta(const float* __restrict__ bias, float* __restrict__ outp) {
    constexpr int Ng = (PH == 1) ? D_FF : D_MODEL;
    constexpr int Kg = (PH == 1) ? D_MODEL : D_FF;
    constexpr int KT = Kg / SK / 64;
    constexpr int BSTG = BN * 128;
    constexpr int OFB = STG3 * ASTG;
    constexpr int WN = BN / 2;
    constexpr int NP = BN / 32;
    constexpr int NJ = BN / 16;
    constexpr int NBC = BN / 32;
    const __nv_bfloat16* A = (PH == 1) ? g_xq : g_hq;
    const __nv_bfloat16* B = (PH == 1) ? g_w1q : g_w2q;
    const float* fa = (PH == 1) ? g_fx : g_fh;
    const float sw = (PH == 1) ? g_s1 : g_s2;
    float* out = (PH == 1) ? g_h : outp;

    extern __shared__ char smem[];
    const uint32_t sb = smem_u32(smem);
    const int tid = threadIdx.x, lane = tid & 31, wid = tid >> 5;
    const int wm = wid & 3, wn = wid >> 2;
    const int bm = blockIdx.y * 128, bn = blockIdx.x * BN;
    const size_t kz0 = (SK > 1) ? (size_t)blockIdx.z * (Kg / SK) : 0;

    uint32_t dAo[4], dBo[NBC];
    const __nv_bfloat16 *srcA[4], *srcB[NBC];
#pragma unroll
    for (int i = 0; i < 4; i++) {
        int c = tid + i * 256, r = c >> 3, c8 = c & 7;
        dAo[i] = swz128(r, c8);
        srcA[i] = A + (size_t)(bm + r) * Kg + kz0 + c8 * 8;
    }
#pragma unroll
    for (int i = 0; i < NBC; i++) {
        int c = tid + i * 256, r = c >> 3, c8 = c & 7;
        dBo[i] = swz128(r, c8);
        srcB[i] = B + (size_t)(bn + r) * Kg + kz0 + c8 * 8;
    }

    const int arow = wm * 32 + ((lane >> 3) & 1) * 8 + (lane & 7);
    const int ka = lane >> 4;
    const int bcol = wn * WN + ((lane >> 4) & 1) * 8 + (lane & 7);
    const int kb = (lane >> 3) & 1;

    uint32_t abase[2]; int asw[2];
#pragma unroll
    for (int mi = 0; mi < 2; mi++) {
        int r = arow + mi * 16;
        abase[mi] = (uint32_t)(r * 128); asw[mi] = r & 7;
    }
    uint32_t bbase[NP]; int bsw[NP];
#pragma unroll
    for (int p = 0; p < NP; p++) {
        int r = bcol + p * 16;
        bbase[p] = (uint32_t)(r * 128); bsw[p] = r & 7;
    }

    float acc[2][NJ][4];
#pragma unroll
    for (int i = 0; i < 2; i++)
#pragma unroll
        for (int j = 0; j < NJ; j++)
#pragma unroll
            for (int r = 0; r < 4; r++) acc[i][j][r] = 0.f;

    auto load_stage = [&](int s) {
        const int buf = s % STG3;
        const size_t ko = (size_t)s * 64;
        const uint32_t sa = sb + buf * ASTG;
        const uint32_t sbB = sb + OFB + buf * BSTG;
#pragma unroll
        for (int i = 0; i < 4; i++) cp16(sa + dAo[i], srcA[i] + ko);
#pragma unroll
        for (int i = 0; i < NBC; i++) cp16(sbB + dBo[i], srcB[i] + ko);
        CP_COMMIT();
    };

    load_stage(0); load_stage(1);

    for (int kt = 0; kt < KT; kt++) {
        const int buf = kt % STG3;
        if (kt + 1 < KT) asm volatile("cp.async.wait_group 1;" ::: "memory");
        else             asm volatile("cp.async.wait_group 0;" ::: "memory");
        __syncthreads();

        if (kt + 2 < KT) load_stage(kt + 2);

        const uint32_t Ab = sb + buf * ASTG;
        const uint32_t Bb = sb + OFB + buf * BSTG;
#pragma unroll
        for (int ks = 0; ks < 4; ks++) {
            uint32_t a[2][4], b[NP][4];
#pragma unroll
            for (int mi = 0; mi < 2; mi++)
                ldsm4(Ab + abase[mi] + (uint32_t)((((ks << 1) | ka) ^ asw[mi]) << 4), a[mi]);
#pragma unroll
            for (int p = 0; p < NP; p++)
                ldsm4(Bb + bbase[p] + (uint32_t)((((ks << 1) | kb) ^ bsw[p]) << 4), b[p]);
#pragma unroll
            for (int mi = 0; mi < 2; mi++)
#pragma unroll
                for (int nj = 0; nj < NJ; nj++)
                    mma_bf16(acc[mi][nj], a[mi], &b[nj >> 1][(nj & 1) * 2]);
        }
    }

    const int g = lane >> 2, tig = lane & 3;
    if (SK > 1) {
        // raw partial store (integer-valued f32) into g_h half blockIdx.z
        float* pp = g_h + (size_t)blockIdx.z * NTOK * D_MODEL;
#pragma unroll
        for (int mi = 0; mi < 2; mi++) {
#pragma unroll
            for (int half = 0; half < 2; half++) {
                const int row = bm + wm * 32 + mi * 16 + g + half * 8;
                float* orow = pp + (size_t)row * Ng;
#pragma unroll
                for (int nj = 0; nj < NJ; nj++) {
                    const int col = bn + wn * WN + nj * 8 + tig * 2;
                    float2 o;
                    o.x = acc[mi][nj][half * 2 + 0];
                    o.y = acc[mi][nj][half * 2 + 1];
                    *(float2*)(orow + col) = o;
                }
            }
        }
        return;
    }

#pragma unroll
    for (int mi = 0; mi < 2; mi++) {
#pragma unroll
        for (int half = 0; half < 2; half++) {
            const int row = bm + wm * 32 + mi * 16 + g + half * 8;
            const float frow = fa[row] * sw;
            float* orow = out + (size_t)row * Ng;
#pragma unroll
            for (int nj = 0; nj < NJ; nj++) {
                const int col = bn + wn * WN + nj * 8 + tig * 2;
                float2 o;
                o.x = acc[mi][nj][half * 2 + 0] * frow + bias[col + 0];
                o.y = acc[mi][nj][half * 2 + 1] * frow + bias[col + 1];
                if (PH == 1) {
                    o.x = 0.5f * o.x * (1.f + erff(o.x * 0.70710678118654752f));
                    o.y = 0.5f * o.y * (1.f + erff(o.y * 0.70710678118654752f));
                }
                *(float2*)(orow + col) = o;
            }
        }
    }
}

// ---------------- split-K reduce: out = (p0+p1)*frow + bias -----------------
// p0+p1 sums two exact integer-valued f32 (< 2^19 each) -> exact; then the
// dequant expression matches the fused epilogue bit-for-bit.
__global__ void __launch_bounds__(256)
k_reduce(const float* __restrict__ bias, float* __restrict__ out) {
    const int i = blockIdx.x * 256 + threadIdx.x;      // float4 index
    const float4* p0 = (const float4*)g_h;
    const float4* p1 = (const float4*)(g_h + (size_t)NTOK * D_MODEL);
    const int row = (i * 4) >> 11;                     // / D_MODEL
    const int col = (i * 4) & (D_MODEL - 1);
    const float frow = g_fh[row] * g_s2;
    float4 a = p0[i], b = p1[i];
    float4 bs = *(const float4*)(bias + col);
    float4 o;
    o.x = (a.x + b.x) * frow + bs.x;
    o.y = (a.y + b.y) * frow + bs.y;
    o.z = (a.z + b.z) * frow + bs.z;
    o.w = (a.w + b.w) * frow + bs.w;
    ((float4*)out)[i] = o;
}

// ---------------- launch ----------------------------------------------------
// Sequence: K1, K2, GEMM1, K3, GEMM2(split-K), reduce.
extern "C" void kernel_launch(void* const* d_in, const int* in_sizes, int n_in,
                              void* d_out, int out_size) {
    const float* x  = (const float*)d_in[0];
    const float* w1 = (const float*)d_in[1];
    const float* b1 = (const float*)d_in[2];
    const float* w2 = (const float*)d_in[3];
    const float* b2 = (const float*)d_in[4];
    float* out = (float*)d_out;

    constexpr int GS = STG3 * (ASTG + 128 * 128);   // 98304 (2 CTAs -> 192K/SM)
    cudaFuncSetAttribute((const void*)k_gemm2cta<1, 128, 1>,
                         cudaFuncAttributeMaxDynamicSharedMemorySize, GS);
    cudaFuncSetAttribute((const void*)k_gemm2cta<2, 128, 2>,
                         cudaFuncAttributeMaxDynamicSharedMemorySize, GS);

    const int n4 = (int)(NW / 4);
    const float invn = 1.f / (float)NW;

    k_fused1<<<NTOK + 1024, 256>>>(x, w1, n4);                                // 0
    k_fused2<<<2048, 256>>>(w1, w2, n4, invn);                                // 1
    k_gemm2cta<1, 128, 1><<<dim3(D_FF / 128, NTOK / 128), 256, GS>>>(b1, nullptr); // 2
    k_fused3<<<NTOK + 1024, 512>>>(w2, n4, invn);                             // 3 <- ncu
    k_gemm2cta<2, 128, 2><<<dim3(D_MODEL / 128, NTOK / 128, 2), 256, GS>>>(b2, nullptr); // 4
    k_reduce<<<(int)(NTOK * (size_t)D_MODEL / 4 / 256), 256>>>(b2, out);      // 5
}